// round 14
// baseline (speedup 1.0000x reference)
#include <cuda_runtime.h>
#include <cuda_fp16.h>
#include <math.h>
#include <stdint.h>

#define TT 2048
#define DD 1024
#define HH 2048
#define EE 8

#define BM 128
#define BN 256
#define BK 32
#define NT 256

// SMEM: A 3 stages of [128 rows x 80B] fp16, B 2 stages of [32 rows x 528B] fp16
#define A_PITCH_B 80
#define B_PITCH_B 528
#define A_BUF_B (BM * A_PITCH_B)           // 10240
#define B_BUF_B (BK * B_PITCH_B)           // 16896
#define SMEM_DYN (3 * A_BUF_B + 2 * B_BUF_B)   // 64512 B

// -------- device scratch (no runtime allocation allowed) --------
__device__ int   g_count[EE];
__device__ int   g_offset[EE];
__device__ int   g_tok[EE * TT];
__device__ int   g_se[2 * TT];
__device__ int   g_sp[2 * TT];
__device__ float g_wt2[2 * TT];
__device__ __align__(16) __half g_x[(size_t)TT * DD];
__device__ __align__(16) __half g_h[(size_t)(2 * TT + BM) * HH];
__device__ __align__(16) float  g_y[(size_t)(2 * TT) * DD];

// ---------------- helpers ----------------
__device__ __forceinline__ uint32_t smem_u32(const void* p) {
    uint32_t a;
    asm("{ .reg .u64 t; cvta.to.shared.u64 t, %1; cvt.u32.u64 %0, t; }" : "=r"(a) : "l"(p));
    return a;
}
__device__ __forceinline__ uint32_t h2u(__half2 h) {
    return *reinterpret_cast<uint32_t*>(&h);
}
#define CP_ASYNC16(dst, src) \
    asm volatile("cp.async.cg.shared.global [%0], [%1], 16;" :: "r"(dst), "l"(src) : "memory")
#define CP_COMMIT()  asm volatile("cp.async.commit_group;" ::: "memory")
#define CP_WAIT(n)   asm volatile("cp.async.wait_group %0;" :: "n"(n) : "memory")

__device__ __forceinline__ void ldsm4(uint32_t* r, uint32_t addr) {
    asm volatile("ldmatrix.sync.aligned.m8n8.x4.shared.b16 {%0,%1,%2,%3}, [%4];"
        : "=r"(r[0]), "=r"(r[1]), "=r"(r[2]), "=r"(r[3]) : "r"(addr));
}
__device__ __forceinline__ void ldsm4t(uint32_t* r, uint32_t addr) {
    asm volatile("ldmatrix.sync.aligned.m8n8.x4.trans.shared.b16 {%0,%1,%2,%3}, [%4];"
        : "=r"(r[0]), "=r"(r[1]), "=r"(r[2]), "=r"(r[3]) : "r"(addr));
}
__device__ __forceinline__ void mma_f16(float* c, const uint32_t* a, const uint32_t* b) {
    asm volatile(
        "mma.sync.aligned.m16n8k16.row.col.f32.f16.f16.f32 "
        "{%0,%1,%2,%3}, {%4,%5,%6,%7}, {%8,%9}, {%0,%1,%2,%3};"
        : "+f"(c[0]), "+f"(c[1]), "+f"(c[2]), "+f"(c[3])
        : "r"(a[0]), "r"(a[1]), "r"(a[2]), "r"(a[3]), "r"(b[0]), "r"(b[1]));
}
__device__ __forceinline__ float gelu_tanh(float v) {
    float x3 = v * v * v;
    float t  = tanhf(0.7978845608028654f * (v + 0.044715f * x3));
    return 0.5f * v * (1.0f + t);
}

// ----------------------------------------------------------------
__global__ void prep_kernel(const float* __restrict__ x) {
    int i = blockIdx.x * blockDim.x + threadIdx.x;
    if (i < EE) g_count[i] = 0;
    const int n4 = TT * DD / 4;
    const int stride = gridDim.x * blockDim.x;
    for (int j = i; j < n4; j += stride) {
        float4 v = reinterpret_cast<const float4*>(x)[j];
        uint2 u = { h2u(__floats2half2_rn(v.x, v.y)), h2u(__floats2half2_rn(v.z, v.w)) };
        reinterpret_cast<uint2*>(g_x)[j] = u;
    }
}

__global__ void gate_kernel(const float* __restrict__ x,
                            const float* __restrict__ Wg,
                            const float* __restrict__ bg,
                            float* __restrict__ out_idx, int write_idx) {
    int warp = (blockIdx.x * blockDim.x + threadIdx.x) >> 5;
    int lane = threadIdx.x & 31;
    if (warp >= TT) return;
    const float* xr = x + (size_t)warp * DD;

    float acc[EE];
#pragma unroll
    for (int e = 0; e < EE; e++) acc[e] = 0.0f;
    for (int d = lane; d < DD; d += 32) {
        float xv = xr[d];
        const float* wr = Wg + (size_t)d * EE;
#pragma unroll
        for (int e = 0; e < EE; e++) acc[e] += xv * wr[e];
    }
#pragma unroll
    for (int off = 16; off > 0; off >>= 1) {
#pragma unroll
        for (int e = 0; e < EE; e++)
            acc[e] += __shfl_xor_sync(0xFFFFFFFFu, acc[e], off);
    }
    if (lane == 0) {
        float v[EE];
#pragma unroll
        for (int e = 0; e < EE; e++) v[e] = acc[e] + bg[e];
        int e0 = 0;
#pragma unroll
        for (int e = 1; e < EE; e++) if (v[e] > v[e0]) e0 = e;
        int e1 = -1;
#pragma unroll
        for (int e = 0; e < EE; e++)
            if (e != e0 && (e1 < 0 || v[e] > v[e1])) e1 = e;

        float a1 = expf(v[e1] - v[e0]);
        float s  = 1.0f + a1;
        float w0 = 1.0f / s;
        float w1 = a1 / s;

        int p0 = atomicAdd(&g_count[e0], 1);
        g_tok[e0 * TT + p0] = warp;
        int p1 = atomicAdd(&g_count[e1], 1);
        g_tok[e1 * TT + p1] = warp;

        g_se[2 * warp] = e0;  g_sp[2 * warp] = p0;  g_wt2[2 * warp] = w0;
        g_se[2 * warp + 1] = e1;  g_sp[2 * warp + 1] = p1;  g_wt2[2 * warp + 1] = w1;

        if (write_idx) {
            out_idx[warp * 2 + 0] = (float)e0;
            out_idx[warp * 2 + 1] = (float)e1;
        }
    }
}

__global__ void prefix_kernel() {
    if (threadIdx.x == 0) {
        int s = 0;
#pragma unroll
        for (int e = 0; e < EE; e++) { g_offset[e] = s; s += g_count[e]; }
    }
}

// ---------------- fp16 HMMA grouped FFN GEMM ----------------
// CTA 128x256, 256 threads = 8 warps (2M x 4N), warp tile 64x64, m16n8k16.
// Fragment-level software pipeline: ks1 frags loaded before ks0 mma; next-slab
// A ks0 frags loaded between mma blocks (A ring stage already resident).
template <bool SECOND>
__global__ void __launch_bounds__(NT, 1)
ffn_kernel(const float* __restrict__ W, const float* __restrict__ bias) {
    const int KDIM = SECOND ? HH : DD;
    const int NDIM = SECOND ? DD : HH;
    const int NS   = KDIM / BK;

    const int e   = blockIdx.x >> 4;
    const int mt_ = blockIdx.x & 15;
    const int cnt = g_count[e];
    const int m0  = mt_ * BM;
    if (m0 >= cnt) return;
    const int n0 = blockIdx.y * BN;
    const int gbase = g_offset[e];

    __shared__ int stok[BM];
    extern __shared__ uint32_t smem[];
    const uint32_t sbaseA = smem_u32(smem);
    const uint32_t sbaseB = sbaseA + 3 * A_BUF_B;

    const int tid  = threadIdx.x;
    const int lane = tid & 31;
    const int wid  = tid >> 5;
    const int wm   = wid & 1;      // 2 warps along M (64 rows)
    const int wn   = wid >> 1;     // 4 warps along N (64 cols)
    const int lr   = lane >> 2;
    const int lc   = lane & 3;

    if (!SECOND) {
        if (tid < BM) {
            int r = m0 + tid;
            stok[tid] = (r < cnt) ? g_tok[e * TT + r] : g_tok[e * TT];
        }
        __syncthreads();
    }

    // ---- A producer: 2 chunks of 16B per thread per slab (row = tid>>1) ----
    const char* Agbase = SECOND ? (const char*)g_h : (const char*)g_x;
    const int arow = tid >> 1;
    uint32_t aoff;
    if (SECOND) aoff = (uint32_t)((gbase + m0 + arow) * HH * 2);
    else        aoff = (uint32_t)(stok[arow] * DD * 2);
    const uint32_t aq   = (uint32_t)((tid & 1) * 32);
    const uint32_t adst = sbaseA + (uint32_t)(arow * A_PITCH_B) + aq;

    // ---- B producer: rows k = (tid>>5)+8i (i<4), n-oct (tid&31)*8 ----
    const float* Wb = W + (size_t)e * KDIM * NDIM + n0 + (tid & 31) * 8;
    const int bk0 = tid >> 5;
    const uint32_t bsts0 = sbaseB + (uint32_t)(bk0 * B_PITCH_B + (tid & 31) * 16);

    // ---- consumer frag addresses ----
    const uint32_t a_lane = sbaseA +
        (uint32_t)((wm * 64 + (lane & 15)) * A_PITCH_B + (lane >> 4) * 16);
    const uint32_t b_lane = sbaseB +
        (uint32_t)(((lane & 7) + ((lane >> 3) & 1) * 8) * B_PITCH_B
                   + (wn * 64 + ((lane >> 4) & 1) * 8) * 2);

    float c[4][8][4];
#pragma unroll
    for (int m = 0; m < 4; m++)
#pragma unroll
        for (int n = 0; n < 8; n++)
#pragma unroll
            for (int j = 0; j < 4; j++) c[m][n][j] = 0.0f;

    // ---- prologue: commit A slabs 0,1; B slab 0 via regs ----
#pragma unroll
    for (int st = 0; st < 2; st++) {
        const uint32_t k0b = (uint32_t)(st * 64);
        CP_ASYNC16(adst + (uint32_t)(st * A_BUF_B),      Agbase + aoff + k0b + aq);
        CP_ASYNC16(adst + (uint32_t)(st * A_BUF_B) + 16, Agbase + aoff + k0b + aq + 16);
        CP_COMMIT();
    }
    {
#pragma unroll
        for (int i = 0; i < 4; i++) {
            const float* wr = Wb + (size_t)(bk0 + 8 * i) * NDIM;
            float4 q0 = *reinterpret_cast<const float4*>(wr);
            float4 q1 = *reinterpret_cast<const float4*>(wr + 4);
            asm volatile("st.shared.v4.b32 [%0], {%1, %2, %3, %4};"
                :: "r"(bsts0 + (uint32_t)(i * 8 * B_PITCH_B)),
                   "r"(h2u(__floats2half2_rn(q0.x, q0.y))), "r"(h2u(__floats2half2_rn(q0.z, q0.w))),
                   "r"(h2u(__floats2half2_rn(q1.x, q1.y))), "r"(h2u(__floats2half2_rn(q1.z, q1.w))));
        }
    }
    CP_WAIT(1);
    __syncthreads();

    // ---- fragment double buffers ----
    uint32_t af[2][4][4];      // [ks][m][frag]
    uint32_t bf[2][8][2];      // [ks][n][frag]

    // preload ks0 frags of slab 0
#pragma unroll
    for (int m = 0; m < 4; m++)
        ldsm4(af[0][m], a_lane + m * (16 * A_PITCH_B));
#pragma unroll
    for (int j = 0; j < 4; j++) {
        uint32_t r[4];
        ldsm4t(r, b_lane + j * 32);
        bf[0][2 * j][0] = r[0];      bf[0][2 * j][1] = r[1];
        bf[0][2 * j + 1][0] = r[2];  bf[0][2 * j + 1][1] = r[3];
    }

    // ---- main loop ----
    uint32_t caOff = 0;
    uint32_t paOff = 2 * A_BUF_B;
    for (int s = 0; s < NS; s++) {
        const uint32_t caNext = (caOff == 2 * A_BUF_B) ? 0 : caOff + A_BUF_B;
        if (s + 2 < NS) {
            const uint32_t k0b = (uint32_t)((s + 2) * 64);
            CP_ASYNC16(adst + paOff,      Agbase + aoff + k0b + aq);
            CP_ASYNC16(adst + paOff + 16, Agbase + aoff + k0b + aq + 16);
        }
        CP_COMMIT();

        const uint32_t aAddr = a_lane + caOff;
        const uint32_t bAddr = b_lane + (uint32_t)((s & 1) * B_BUF_B);

        // load ks1 frags of current slab (latency hidden under ks0 mma)
#pragma unroll
        for (int m = 0; m < 4; m++)
            ldsm4(af[1][m], aAddr + m * (16 * A_PITCH_B) + 32);
#pragma unroll
        for (int j = 0; j < 4; j++) {
            uint32_t r[4];
            ldsm4t(r, bAddr + 16 * B_PITCH_B + j * 32);
            bf[1][2 * j][0] = r[0];      bf[1][2 * j][1] = r[1];
            bf[1][2 * j + 1][0] = r[2];  bf[1][2 * j + 1][1] = r[3];
        }

        // B(s+1) global prefetch (independent long-latency)
        float4 p0, p1, p2, p3, p4, p5, p6, p7;
        if (s + 1 < NS) {
            const int kw = (s + 1) * BK;
            const float* w0 = Wb + (size_t)(kw + bk0) * NDIM;
            const float* w1 = Wb + (size_t)(kw + bk0 + 8) * NDIM;
            const float* w2 = Wb + (size_t)(kw + bk0 + 16) * NDIM;
            const float* w3 = Wb + (size_t)(kw + bk0 + 24) * NDIM;
            p0 = *reinterpret_cast<const float4*>(w0);
            p1 = *reinterpret_cast<const float4*>(w0 + 4);
            p2 = *reinterpret_cast<const float4*>(w1);
            p3 = *reinterpret_cast<const float4*>(w1 + 4);
            p4 = *reinterpret_cast<const float4*>(w2);
            p5 = *reinterpret_cast<const float4*>(w2 + 4);
            p6 = *reinterpret_cast<const float4*>(w3);
            p7 = *reinterpret_cast<const float4*>(w3 + 4);
        }

        // mma ks0
#pragma unroll
        for (int m = 0; m < 4; m++)
#pragma unroll
            for (int n = 0; n < 8; n++)
                mma_f16(c[m][n], af[0][m], bf[0][n]);

        // load next slab's A ks0 frags (A ring stage s+1 already resident)
        if (s + 1 < NS) {
#pragma unroll
            for (int m = 0; m < 4; m++)
                ldsm4(af[0][m], a_lane + caNext + m * (16 * A_PITCH_B));
        }

        // mma ks1
#pragma unroll
        for (int m = 0; m < 4; m++)
#pragma unroll
            for (int n = 0; n < 8; n++)
                mma_f16(c[m][n], af[1][m], bf[1][n]);

        if (s + 1 < NS) {
            const uint32_t bsts = bsts0 + (uint32_t)(((s + 1) & 1) * B_BUF_B);
            asm volatile("st.shared.v4.b32 [%0], {%1, %2, %3, %4};"
                :: "r"(bsts),
                   "r"(h2u(__floats2half2_rn(p0.x, p0.y))), "r"(h2u(__floats2half2_rn(p0.z, p0.w))),
                   "r"(h2u(__floats2half2_rn(p1.x, p1.y))), "r"(h2u(__floats2half2_rn(p1.z, p1.w))));
            asm volatile("st.shared.v4.b32 [%0], {%1, %2, %3, %4};"
                :: "r"(bsts + (uint32_t)(8 * B_PITCH_B)),
                   "r"(h2u(__floats2half2_rn(p2.x, p2.y))), "r"(h2u(__floats2half2_rn(p2.z, p2.w))),
                   "r"(h2u(__floats2half2_rn(p3.x, p3.y))), "r"(h2u(__floats2half2_rn(p3.z, p3.w))));
            asm volatile("st.shared.v4.b32 [%0], {%1, %2, %3, %4};"
                :: "r"(bsts + (uint32_t)(16 * B_PITCH_B)),
                   "r"(h2u(__floats2half2_rn(p4.x, p4.y))), "r"(h2u(__floats2half2_rn(p4.z, p4.w))),
                   "r"(h2u(__floats2half2_rn(p5.x, p5.y))), "r"(h2u(__floats2half2_rn(p5.z, p5.w))));
            asm volatile("st.shared.v4.b32 [%0], {%1, %2, %3, %4};"
                :: "r"(bsts + (uint32_t)(24 * B_PITCH_B)),
                   "r"(h2u(__floats2half2_rn(p6.x, p6.y))), "r"(h2u(__floats2half2_rn(p6.z, p6.w))),
                   "r"(h2u(__floats2half2_rn(p7.x, p7.y))), "r"(h2u(__floats2half2_rn(p7.z, p7.w))));
            CP_WAIT(1);
            __syncthreads();

            // load B ks0 frags of next slab (only post-barrier dependency)
            const uint32_t bNext = b_lane + (uint32_t)(((s + 1) & 1) * B_BUF_B);
#pragma unroll
            for (int j = 0; j < 4; j++) {
                uint32_t r[4];
                ldsm4t(r, bNext + j * 32);
                bf[0][2 * j][0] = r[0];      bf[0][2 * j][1] = r[1];
                bf[0][2 * j + 1][0] = r[2];  bf[0][2 * j + 1][1] = r[3];
            }
        }

        caOff = caNext;
        paOff = (paOff == 2 * A_BUF_B) ? 0 : paOff + A_BUF_B;
    }

    // ---- epilogue ----
#pragma unroll
    for (int n = 0; n < 8; n++) {
        const int col = n0 + wn * 64 + n * 8 + 2 * lc;
        const float bv0 = bias[e * NDIM + col];
        const float bv1 = bias[e * NDIM + col + 1];
#pragma unroll
        for (int m = 0; m < 4; m++) {
#pragma unroll
            for (int h = 0; h < 2; h++) {
                const int rloc = wm * 64 + m * 16 + h * 8 + lr;
                const int rg   = m0 + rloc;
                if (rg < cnt) {
                    float v0 = c[m][n][2 * h + 0] + bv0;
                    float v1 = c[m][n][2 * h + 1] + bv1;
                    if (!SECOND) {
                        __half2 o = __floats2half2_rn(gelu_tanh(v0), gelu_tanh(v1));
                        *reinterpret_cast<__half2*>(&g_h[(size_t)(gbase + rg) * HH + col]) = o;
                    } else {
                        float2 o = { v0, v1 };
                        *reinterpret_cast<float2*>(&g_y[(size_t)(gbase + rg) * DD + col]) = o;
                    }
                }
            }
        }
    }
}

// combine: out[t] = w0*y[slot0] + w1*y[slot1]
__global__ void combine_kernel(float* __restrict__ out) {
    const int t = blockIdx.x;
    __shared__ int   s0, s1;
    __shared__ float w0, w1;
    if (threadIdx.x == 0) {
        s0 = g_offset[g_se[2 * t]]     + g_sp[2 * t];
        s1 = g_offset[g_se[2 * t + 1]] + g_sp[2 * t + 1];
        w0 = g_wt2[2 * t];
        w1 = g_wt2[2 * t + 1];
    }
    __syncthreads();
    const int d = threadIdx.x;
    float4 y0 = reinterpret_cast<const float4*>(g_y + (size_t)s0 * DD)[d];
    float4 y1 = reinterpret_cast<const float4*>(g_y + (size_t)s1 * DD)[d];
    float4 o = { w0 * y0.x + w1 * y1.x, w0 * y0.y + w1 * y1.y,
                 w0 * y0.z + w1 * y1.z, w0 * y0.w + w1 * y1.w };
    reinterpret_cast<float4*>(out + (size_t)t * DD)[d] = o;
}

// ----------------------------------------------------------------
extern "C" void kernel_launch(void* const* d_in, const int* in_sizes, int n_in,
                              void* d_out, int out_size) {
    const float* x  = (const float*)d_in[0];
    const float* Wg = (const float*)d_in[1];
    const float* bg = (const float*)d_in[2];
    const float* W1 = (const float*)d_in[3];
    const float* b1 = (const float*)d_in[4];
    const float* W2 = (const float*)d_in[5];
    const float* b2 = (const float*)d_in[6];
    float* out = (float*)d_out;

    const int write_idx = (out_size >= TT * DD + 2 * TT) ? 1 : 0;
    float* out_idx = out + (size_t)TT * DD;

    static int attr_done = 0;
    if (!attr_done) {
        cudaFuncSetAttribute(ffn_kernel<false>, cudaFuncAttributeMaxDynamicSharedMemorySize, SMEM_DYN);
        cudaFuncSetAttribute(ffn_kernel<true>,  cudaFuncAttributeMaxDynamicSharedMemorySize, SMEM_DYN);
        attr_done = 1;
    }

    prep_kernel<<<512, 256>>>(x);
    gate_kernel<<<(TT * 32 + 255) / 256, 256>>>(x, Wg, bg, out_idx, write_idx);
    prefix_kernel<<<1, 32>>>();

    ffn_kernel<false><<<dim3(EE * 16, HH / BN), NT, SMEM_DYN>>>(W1, b1);
    ffn_kernel<true ><<<dim3(EE * 16, DD / BN), NT, SMEM_DYN>>>(W2, b2);

    combine_kernel<<<TT, 256>>>(out);
}

// round 15
// speedup vs baseline: 1.3063x; 1.3063x over previous
#include <cuda_runtime.h>
#include <cuda_fp16.h>
#include <math.h>
#include <stdint.h>

#define TT 2048
#define DD 1024
#define HH 2048
#define EE 8

#define BM 128
#define BN 256
#define BK 32
#define NT 256

// SMEM: 3 stages A [128 x 80B] + 3 stages B [32 x 528B]
#define A_PITCH_B 80
#define B_PITCH_B 528
#define A_BUF_B (BM * A_PITCH_B)           // 10240
#define B_BUF_B (BK * B_PITCH_B)           // 16896
#define SMEM_DYN (3 * (A_BUF_B + B_BUF_B))   // 81408 B

// -------- device scratch (no runtime allocation allowed) --------
__device__ int   g_count[EE];
__device__ int   g_offset[EE];
__device__ int   g_tok[EE * TT];
__device__ int   g_se[2 * TT];
__device__ int   g_sp[2 * TT];
__device__ float g_wt2[2 * TT];
__device__ __align__(16) __half g_x[(size_t)TT * DD];
__device__ __align__(16) __half g_w1h[(size_t)EE * DD * HH];   // fp16 W1
__device__ __align__(16) __half g_w2h[(size_t)EE * HH * DD];   // fp16 W2
__device__ __align__(16) __half g_h[(size_t)(2 * TT + BM) * HH];
__device__ __align__(16) float  g_y[(size_t)(2 * TT) * DD];

// ---------------- helpers ----------------
__device__ __forceinline__ uint32_t smem_u32(const void* p) {
    uint32_t a;
    asm("{ .reg .u64 t; cvta.to.shared.u64 t, %1; cvt.u32.u64 %0, t; }" : "=r"(a) : "l"(p));
    return a;
}
__device__ __forceinline__ uint32_t h2u(__half2 h) {
    return *reinterpret_cast<uint32_t*>(&h);
}
#define CP_ASYNC16(dst, src) \
    asm volatile("cp.async.cg.shared.global [%0], [%1], 16;" :: "r"(dst), "l"(src) : "memory")
#define CP_COMMIT()  asm volatile("cp.async.commit_group;" ::: "memory")
#define CP_WAIT(n)   asm volatile("cp.async.wait_group %0;" :: "n"(n) : "memory")

__device__ __forceinline__ void ldsm4(uint32_t* r, uint32_t addr) {
    asm volatile("ldmatrix.sync.aligned.m8n8.x4.shared.b16 {%0,%1,%2,%3}, [%4];"
        : "=r"(r[0]), "=r"(r[1]), "=r"(r[2]), "=r"(r[3]) : "r"(addr));
}
__device__ __forceinline__ void ldsm4t(uint32_t* r, uint32_t addr) {
    asm volatile("ldmatrix.sync.aligned.m8n8.x4.trans.shared.b16 {%0,%1,%2,%3}, [%4];"
        : "=r"(r[0]), "=r"(r[1]), "=r"(r[2]), "=r"(r[3]) : "r"(addr));
}
__device__ __forceinline__ void mma_f16(float* c, const uint32_t* a, const uint32_t* b) {
    asm volatile(
        "mma.sync.aligned.m16n8k16.row.col.f32.f16.f16.f32 "
        "{%0,%1,%2,%3}, {%4,%5,%6,%7}, {%8,%9}, {%0,%1,%2,%3};"
        : "+f"(c[0]), "+f"(c[1]), "+f"(c[2]), "+f"(c[3])
        : "r"(a[0]), "r"(a[1]), "r"(a[2]), "r"(a[3]), "r"(b[0]), "r"(b[1]));
}
__device__ __forceinline__ float gelu_tanh(float v) {
    float x3 = v * v * v;
    float t  = tanhf(0.7978845608028654f * (v + 0.044715f * x3));
    return 0.5f * v * (1.0f + t);
}

// ----------------------------------------------------------------
// prep: fp16-round x, W1, W2 into device tables; zero counters
__global__ void prep_kernel(const float* __restrict__ x,
                            const float* __restrict__ W1,
                            const float* __restrict__ W2) {
    const int i = blockIdx.x * blockDim.x + threadIdx.x;
    if (i < EE) g_count[i] = 0;
    const int stride = gridDim.x * blockDim.x;

    const int nx = TT * DD / 4;
    for (int j = i; j < nx; j += stride) {
        float4 v = reinterpret_cast<const float4*>(x)[j];
        uint2 u = { h2u(__floats2half2_rn(v.x, v.y)), h2u(__floats2half2_rn(v.z, v.w)) };
        reinterpret_cast<uint2*>(g_x)[j] = u;
    }
    const int nw = EE * DD * HH / 4;
    for (int j = i; j < nw; j += stride) {
        float4 v = reinterpret_cast<const float4*>(W1)[j];
        uint2 u = { h2u(__floats2half2_rn(v.x, v.y)), h2u(__floats2half2_rn(v.z, v.w)) };
        reinterpret_cast<uint2*>(g_w1h)[j] = u;
    }
    for (int j = i; j < nw; j += stride) {
        float4 v = reinterpret_cast<const float4*>(W2)[j];
        uint2 u = { h2u(__floats2half2_rn(v.x, v.y)), h2u(__floats2half2_rn(v.z, v.w)) };
        reinterpret_cast<uint2*>(g_w2h)[j] = u;
    }
}

__global__ void gate_kernel(const float* __restrict__ x,
                            const float* __restrict__ Wg,
                            const float* __restrict__ bg,
                            float* __restrict__ out_idx, int write_idx) {
    int warp = (blockIdx.x * blockDim.x + threadIdx.x) >> 5;
    int lane = threadIdx.x & 31;
    if (warp >= TT) return;
    const float* xr = x + (size_t)warp * DD;

    float acc[EE];
#pragma unroll
    for (int e = 0; e < EE; e++) acc[e] = 0.0f;
    for (int d = lane; d < DD; d += 32) {
        float xv = xr[d];
        const float* wr = Wg + (size_t)d * EE;
#pragma unroll
        for (int e = 0; e < EE; e++) acc[e] += xv * wr[e];
    }
#pragma unroll
    for (int off = 16; off > 0; off >>= 1) {
#pragma unroll
        for (int e = 0; e < EE; e++)
            acc[e] += __shfl_xor_sync(0xFFFFFFFFu, acc[e], off);
    }
    if (lane == 0) {
        float v[EE];
#pragma unroll
        for (int e = 0; e < EE; e++) v[e] = acc[e] + bg[e];
        int e0 = 0;
#pragma unroll
        for (int e = 1; e < EE; e++) if (v[e] > v[e0]) e0 = e;
        int e1 = -1;
#pragma unroll
        for (int e = 0; e < EE; e++)
            if (e != e0 && (e1 < 0 || v[e] > v[e1])) e1 = e;

        float a1 = expf(v[e1] - v[e0]);
        float s  = 1.0f + a1;
        float w0 = 1.0f / s;
        float w1 = a1 / s;

        int p0 = atomicAdd(&g_count[e0], 1);
        g_tok[e0 * TT + p0] = warp;
        int p1 = atomicAdd(&g_count[e1], 1);
        g_tok[e1 * TT + p1] = warp;

        g_se[2 * warp] = e0;  g_sp[2 * warp] = p0;  g_wt2[2 * warp] = w0;
        g_se[2 * warp + 1] = e1;  g_sp[2 * warp + 1] = p1;  g_wt2[2 * warp + 1] = w1;

        if (write_idx) {
            out_idx[warp * 2 + 0] = (float)e0;
            out_idx[warp * 2 + 1] = (float)e1;
        }
    }
}

__global__ void prefix_kernel() {
    if (threadIdx.x == 0) {
        int s = 0;
#pragma unroll
        for (int e = 0; e < EE; e++) { g_offset[e] = s; s += g_count[e]; }
    }
}

// ---------------- fp16 HMMA grouped FFN GEMM ----------------
// CTA 128x256, 256 threads = 8 warps (2M x 4N), warp tile 64x64, m16n8k16.
// A AND B both stream via cp.async (fp16 sources), 3-stage ring, distance-2
// prefetch, wait_group(1): ~2 slabs of DRAM-latency cover per operand.
template <bool SECOND>
__global__ void __launch_bounds__(NT, 1)
ffn_kernel(const float* __restrict__ bias) {
    const int KDIM = SECOND ? HH : DD;
    const int NDIM = SECOND ? DD : HH;
    const int NS   = KDIM / BK;

    const int e   = blockIdx.x >> 4;
    const int mt_ = blockIdx.x & 15;
    const int cnt = g_count[e];
    const int m0  = mt_ * BM;
    if (m0 >= cnt) return;
    const int n0 = blockIdx.y * BN;
    const int gbase = g_offset[e];

    __shared__ int stok[BM];
    extern __shared__ uint32_t smem[];
    const uint32_t sbaseA = smem_u32(smem);
    const uint32_t sbaseB = sbaseA + 3 * A_BUF_B;

    const int tid  = threadIdx.x;
    const int lane = tid & 31;
    const int wid  = tid >> 5;
    const int wm   = wid & 1;      // 2 warps along M (64 rows)
    const int wn   = wid >> 1;     // 4 warps along N (64 cols)
    const int lr   = lane >> 2;
    const int lc   = lane & 3;

    if (!SECOND) {
        if (tid < BM) {
            int r = m0 + tid;
            stok[tid] = (r < cnt) ? g_tok[e * TT + r] : g_tok[e * TT];
        }
        __syncthreads();
    }

    // ---- A producer: 2 x 16B per thread per slab (row = tid>>1) ----
    const char* Agbase = SECOND ? (const char*)g_h : (const char*)g_x;
    const int arow = tid >> 1;
    uint32_t aoff;
    if (SECOND) aoff = (uint32_t)((gbase + m0 + arow) * HH * 2);
    else        aoff = (uint32_t)(stok[arow] * DD * 2);
    const uint32_t aq   = (uint32_t)((tid & 1) * 32);
    const uint32_t adst = sbaseA + (uint32_t)(arow * A_PITCH_B) + aq;

    // ---- B producer: 4 x 16B per thread per slab ----
    // thread t: k-row = t>>3 (0..31), 64B base (t&7)*64 within the 512B row
    const char* Bgbase = SECOND ? (const char*)g_w2h : (const char*)g_w1h;
    const uint32_t boff = (uint32_t)((size_t)e * KDIM * NDIM * 2 + (size_t)(tid >> 3) * NDIM * 2
                                     + (size_t)n0 * 2 + (uint32_t)((tid & 7) * 64));
    const uint32_t brow_stride = (uint32_t)(NDIM * 2);   // bytes per k-row in global
    const uint32_t bdst = sbaseB + (uint32_t)((tid >> 3) * B_PITCH_B + (tid & 7) * 64);

    // ---- consumer frag addresses ----
    const uint32_t a_lane = sbaseA +
        (uint32_t)((wm * 64 + (lane & 15)) * A_PITCH_B + (lane >> 4) * 16);
    const uint32_t b_lane = sbaseB +
        (uint32_t)(((lane & 7) + ((lane >> 3) & 1) * 8) * B_PITCH_B
                   + (wn * 64 + ((lane >> 4) & 1) * 8) * 2);

    float c[4][8][4];
#pragma unroll
    for (int m = 0; m < 4; m++)
#pragma unroll
        for (int n = 0; n < 8; n++)
#pragma unroll
            for (int j = 0; j < 4; j++) c[m][n][j] = 0.0f;

    // ---- prologue: commit stages 0 and 1 (A + B jointly) ----
#pragma unroll
    for (int st = 0; st < 2; st++) {
        const uint32_t akb = (uint32_t)(st * 64);              // A: 32 halfs = 64B per slab
        CP_ASYNC16(adst + (uint32_t)(st * A_BUF_B),      Agbase + aoff + akb + aq);
        CP_ASYNC16(adst + (uint32_t)(st * A_BUF_B) + 16, Agbase + aoff + akb + aq + 16);
        const uint32_t bkb = (uint32_t)(st * BK) * brow_stride; // B: advance 32 k-rows
#pragma unroll
        for (int j = 0; j < 4; j++)
            CP_ASYNC16(bdst + (uint32_t)(st * B_BUF_B) + (uint32_t)(j * 16),
                       Bgbase + boff + bkb + (uint32_t)(j * 16));
        CP_COMMIT();
    }
    CP_WAIT(1);
    __syncthreads();

    // ---- main loop ----
    uint32_t caOffA = 0,            caOffB = 0;
    uint32_t paOffA = 2 * A_BUF_B,  paOffB = 2 * B_BUF_B;
    for (int s = 0; s < NS; s++) {
        if (s + 2 < NS) {
            const uint32_t akb = (uint32_t)((s + 2) * 64);
            CP_ASYNC16(adst + paOffA,      Agbase + aoff + akb + aq);
            CP_ASYNC16(adst + paOffA + 16, Agbase + aoff + akb + aq + 16);
            const uint32_t bkb = (uint32_t)((s + 2) * BK) * brow_stride;
#pragma unroll
            for (int j = 0; j < 4; j++)
                CP_ASYNC16(bdst + paOffB + (uint32_t)(j * 16),
                           Bgbase + boff + bkb + (uint32_t)(j * 16));
        }
        CP_COMMIT();

        // compute slab s
        const uint32_t aAddr = a_lane + caOffA;
        const uint32_t bAddr = b_lane + caOffB;
#pragma unroll
        for (int ks = 0; ks < 2; ks++) {
            uint32_t a[4][4];
#pragma unroll
            for (int m = 0; m < 4; m++)
                ldsm4(a[m], aAddr + m * (16 * A_PITCH_B) + ks * 32);
            uint32_t b[8][2];
#pragma unroll
            for (int j = 0; j < 4; j++) {
                uint32_t r[4];
                ldsm4t(r, bAddr + ks * (16 * B_PITCH_B) + j * 32);
                b[2 * j][0] = r[0];      b[2 * j][1] = r[1];
                b[2 * j + 1][0] = r[2];  b[2 * j + 1][1] = r[3];
            }
#pragma unroll
            for (int m = 0; m < 4; m++)
#pragma unroll
                for (int n = 0; n < 8; n++)
                    mma_f16(c[m][n], a[m], b[n]);
        }

        if (s + 1 < NS) {
            CP_WAIT(1);
            __syncthreads();
        }

        caOffA = (caOffA == 2 * A_BUF_B) ? 0 : caOffA + A_BUF_B;
        caOffB = (caOffB == 2 * B_BUF_B) ? 0 : caOffB + B_BUF_B;
        paOffA = (paOffA == 2 * A_BUF_B) ? 0 : paOffA + A_BUF_B;
        paOffB = (paOffB == 2 * B_BUF_B) ? 0 : paOffB + B_BUF_B;
    }

    // ---- epilogue ----
#pragma unroll
    for (int n = 0; n < 8; n++) {
        const int col = n0 + wn * 64 + n * 8 + 2 * lc;
        const float bv0 = bias[e * NDIM + col];
        const float bv1 = bias[e * NDIM + col + 1];
#pragma unroll
        for (int m = 0; m < 4; m++) {
#pragma unroll
            for (int h = 0; h < 2; h++) {
                const int rloc = wm * 64 + m * 16 + h * 8 + lr;
                const int rg   = m0 + rloc;
                if (rg < cnt) {
                    float v0 = c[m][n][2 * h + 0] + bv0;
                    float v1 = c[m][n][2 * h + 1] + bv1;
                    if (!SECOND) {
                        __half2 o = __floats2half2_rn(gelu_tanh(v0), gelu_tanh(v1));
                        *reinterpret_cast<__half2*>(&g_h[(size_t)(gbase + rg) * HH + col]) = o;
                    } else {
                        float2 o = { v0, v1 };
                        *reinterpret_cast<float2*>(&g_y[(size_t)(gbase + rg) * DD + col]) = o;
                    }
                }
            }
        }
    }
}

// combine: out[t] = w0*y[slot0] + w1*y[slot1]
__global__ void combine_kernel(float* __restrict__ out) {
    const int t = blockIdx.x;
    __shared__ int   s0, s1;
    __shared__ float w0, w1;
    if (threadIdx.x == 0) {
        s0 = g_offset[g_se[2 * t]]     + g_sp[2 * t];
        s1 = g_offset[g_se[2 * t + 1]] + g_sp[2 * t + 1];
        w0 = g_wt2[2 * t];
        w1 = g_wt2[2 * t + 1];
    }
    __syncthreads();
    const int d = threadIdx.x;
    float4 y0 = reinterpret_cast<const float4*>(g_y + (size_t)s0 * DD)[d];
    float4 y1 = reinterpret_cast<const float4*>(g_y + (size_t)s1 * DD)[d];
    float4 o = { w0 * y0.x + w1 * y1.x, w0 * y0.y + w1 * y1.y,
                 w0 * y0.z + w1 * y1.z, w0 * y0.w + w1 * y1.w };
    reinterpret_cast<float4*>(out + (size_t)t * DD)[d] = o;
}

// ----------------------------------------------------------------
extern "C" void kernel_launch(void* const* d_in, const int* in_sizes, int n_in,
                              void* d_out, int out_size) {
    const float* x  = (const float*)d_in[0];
    const float* Wg = (const float*)d_in[1];
    const float* bg = (const float*)d_in[2];
    const float* W1 = (const float*)d_in[3];
    const float* b1 = (const float*)d_in[4];
    const float* W2 = (const float*)d_in[5];
    const float* b2 = (const float*)d_in[6];
    float* out = (float*)d_out;

    const int write_idx = (out_size >= TT * DD + 2 * TT) ? 1 : 0;
    float* out_idx = out + (size_t)TT * DD;

    static int attr_done = 0;
    if (!attr_done) {
        cudaFuncSetAttribute(ffn_kernel<false>, cudaFuncAttributeMaxDynamicSharedMemorySize, SMEM_DYN);
        cudaFuncSetAttribute(ffn_kernel<true>,  cudaFuncAttributeMaxDynamicSharedMemorySize, SMEM_DYN);
        attr_done = 1;
    }

    prep_kernel<<<2048, 256>>>(x, W1, W2);
    gate_kernel<<<(TT * 32 + 255) / 256, 256>>>(x, Wg, bg, out_idx, write_idx);
    prefix_kernel<<<1, 32>>>();

    ffn_kernel<false><<<dim3(EE * 16, HH / BN), NT, SMEM_DYN>>>(b1);
    ffn_kernel<true ><<<dim3(EE * 16, DD / BN), NT, SMEM_DYN>>>(b2);

    combine_kernel<<<TT, 256>>>(out);
}